// round 6
// baseline (speedup 1.0000x reference)
#include <cuda_runtime.h>
#include <cuda_bf16.h>
#include <math.h>
#include <stdint.h>

// ---------------- problem constants (fixed shapes) ----------------
#define B_   8
#define T_   1024
#define C_   768
#define H_   12
#define HS_  64
#define PH_  32
#define PW_  32
#define NR_  (B_ * T_)          // 8192 rows
#define NC_  ((size_t)NR_ * C_) // 6291456 elems
#define WSZ_ ((size_t)C_ * C_)  // 589824

// ---------------- scratch ----------------
__device__ __align__(16) float g_scratch[14 * NC_ + (size_t)NR_ * 160 + (size_t)NR_ * 64 + (size_t)NR_ * H_];
__device__ __align__(16) __nv_bfloat16 g_acthi[4 * NC_];   // k,v,r,g (slots 0..3)
__device__ __align__(16) __nv_bfloat16 g_actlo[4 * NC_];
__device__ __align__(16) __nv_bfloat16 g_w5hi[5 * WSZ_];   // W_r,W_k,W_v,W_g,W_o
__device__ __align__(16) __nv_bfloat16 g_w5lo[5 * WSZ_];

#define OFF_XX   ((size_t)0)
#define OFF_XXX  (OFF_XX  + NC_)
#define OFF_T5   (OFF_XXX + NC_)
#define OFF_XW   (OFF_T5  + (size_t)NR_ * 160)
#define OFF_R    (OFF_XW  + NC_)
#define OFF_K    (OFF_R   + NC_)
#define OFF_V    (OFF_K   + NC_)
#define OFF_G    (OFF_V   + NC_)
#define OFF_H1   (OFF_G   + NC_)
#define OFF_WDEC (OFF_H1  + (size_t)NR_ * 64)
#define OFF_Y    (OFF_WDEC+ NC_)
#define OFF_RUK  (OFF_Y   + NC_)

// ========================= helpers ==========================
__device__ __forceinline__ uint32_t smem_u32(const void* p) {
    uint32_t a;
    asm("{ .reg .u64 t; cvta.to.shared.u64 t, %1; cvt.u32.u64 %0, t; }" : "=r"(a) : "l"(p));
    return a;
}
__device__ __forceinline__ void ldsm_x4(uint32_t* r, uint32_t addr) {
    asm volatile("ldmatrix.sync.aligned.m8n8.x4.shared.b16 {%0,%1,%2,%3}, [%4];"
                 : "=r"(r[0]), "=r"(r[1]), "=r"(r[2]), "=r"(r[3]) : "r"(addr));
}
__device__ __forceinline__ void mma_bf16(float* c, const uint32_t* a, uint32_t b0, uint32_t b1) {
    asm volatile("mma.sync.aligned.m16n8k16.row.col.f32.bf16.bf16.f32 "
                 "{%0,%1,%2,%3}, {%4,%5,%6,%7}, {%8,%9}, {%0,%1,%2,%3};"
                 : "+f"(c[0]), "+f"(c[1]), "+f"(c[2]), "+f"(c[3])
                 : "r"(a[0]), "r"(a[1]), "r"(a[2]), "r"(a[3]), "r"(b0), "r"(b1));
}
__device__ __forceinline__ void cp_async16(uint32_t dst, const void* src) {
    asm volatile("cp.async.cg.shared.global [%0], [%1], 16;" :: "r"(dst), "l"(src));
}
#define CP_COMMIT() asm volatile("cp.async.commit_group;" ::: "memory")
#define CP_WAIT1()  asm volatile("cp.async.wait_group 1;" ::: "memory")
#define CP_WAIT0()  asm volatile("cp.async.wait_group 0;" ::: "memory")

// ==========================================================================
// bf16-split tensor-core GEMM (mma.sync + cp.async, 3-stage ring):
//   C[8192,768] = epi( A @ W^T ),  D = Ahi*Whi + Alo*Whi + Ahi*Wlo
//   virtual K' = 2304 handled as 36 chunks of 64 cols.
// Block 128x128, 256 thr (8 warps 2x4), one __syncthreads per chunk.
// Smem per stage: A(8 planes) + B(8 planes), plane = 128 rows x 16B, stride 2080.
// ==========================================================================
#define PLANE_   2080
#define TILE_    (8 * PLANE_)        // 16640
#define STAGE_   (2 * TILE_)         // 33280
#define SMEM_MMA (3 * STAGE_)        // 99840

__global__ void __launch_bounds__(256, 2)
k_gemm_mma(const __nv_bfloat16* __restrict__ Ahi, const __nv_bfloat16* __restrict__ Alo,
           const __nv_bfloat16* __restrict__ Whi, const __nv_bfloat16* __restrict__ Wlo,
           float* __restrict__ Cmat, int doRelu)
{
    extern __shared__ __align__(16) char sm[];
    const uint32_t sb = smem_u32(sm);
    const int tid  = threadIdx.x;
    const int warp = tid >> 5;
    const int lane = tid & 31;
    const int m0 = blockIdx.y * 128;
    const int n0 = blockIdx.x * 128;
    const int wm = warp >> 2;        // 0..1
    const int wn = warp & 3;         // 0..3
    const int lgrp = lane >> 3;      // 0..3
    const int lrl  = lane & 7;
    const int ldrow = tid >> 1;      // 0..127
    const int cb0   = (tid & 1) * 4; // chunk 0..3 or 4..7

    float acc[4][4][4];
#pragma unroll
    for (int i = 0; i < 4; i++)
#pragma unroll
        for (int j = 0; j < 4; j++)
#pragma unroll
            for (int q = 0; q < 4; q++) acc[i][j][q] = 0.f;

#define LOADST(c_, s_)                                                          \
    {                                                                           \
        const int seg_ = (c_) / 12;                                             \
        const int kc_  = ((c_) % 12) * 64;                                      \
        const __nv_bfloat16* Ag = (seg_ == 1) ? Alo : Ahi;                      \
        const __nv_bfloat16* Bg = (seg_ == 2) ? Wlo : Whi;                      \
        const __nv_bfloat16* ap = Ag + (size_t)(m0 + ldrow) * C_ + kc_ + cb0 * 8; \
        const __nv_bfloat16* bp = Bg + (size_t)(n0 + ldrow) * C_ + kc_ + cb0 * 8; \
        uint32_t ad = sb + (s_) * STAGE_ + cb0 * PLANE_ + ldrow * 16;           \
        uint32_t bd = ad + TILE_;                                               \
        _Pragma("unroll")                                                       \
        for (int j = 0; j < 4; j++) {                                           \
            cp_async16(ad + j * PLANE_, ap + j * 8);                            \
            cp_async16(bd + j * PLANE_, bp + j * 8);                            \
        }                                                                       \
        CP_COMMIT();                                                            \
    }

    LOADST(0, 0);
    LOADST(1, 1);

    for (int c = 0; c < 36; c++) {
        if (c < 34) { CP_WAIT1(); } else { CP_WAIT0(); }
        __syncthreads();
        if (c + 2 < 36) LOADST(c + 2, (c + 2) % 3);

        const uint32_t abase = sb + (c % 3) * STAGE_;
        const uint32_t bbase = abase + TILE_;

#pragma unroll
        for (int kk = 0; kk < 4; kk++) {
            uint32_t afr[4][4], bfr[2][4];
#pragma unroll
            for (int mt = 0; mt < 4; mt++) {
                int row   = wm * 64 + mt * 16 + (lgrp & 1) * 8 + lrl;
                int chunk = kk * 2 + (lgrp >> 1);
                ldsm_x4(afr[mt], abase + chunk * PLANE_ + row * 16);
            }
#pragma unroll
            for (int nt = 0; nt < 2; nt++) {
                int nr    = wn * 32 + nt * 16 + (lgrp >> 1) * 8 + lrl;
                int chunk = kk * 2 + (lgrp & 1);
                ldsm_x4(bfr[nt], bbase + chunk * PLANE_ + nr * 16);
            }
#pragma unroll
            for (int mt = 0; mt < 4; mt++)
#pragma unroll
                for (int ng = 0; ng < 4; ng++)
                    mma_bf16(acc[mt][ng], afr[mt], bfr[ng >> 1][(ng & 1) * 2 + 0],
                             bfr[ng >> 1][(ng & 1) * 2 + 1]);
        }
    }
#undef LOADST

    // ---- epilogue ----
#pragma unroll
    for (int mt = 0; mt < 4; mt++) {
        const int r0 = m0 + wm * 64 + mt * 16 + (lane >> 2);
#pragma unroll
        for (int ng = 0; ng < 4; ng++) {
            const int col = n0 + wn * 32 + ng * 8 + (lane & 3) * 2;
            float c0 = acc[mt][ng][0], c1 = acc[mt][ng][1];
            float c2 = acc[mt][ng][2], c3 = acc[mt][ng][3];
            if (doRelu) {
                c0 = fmaxf(c0, 0.f); c1 = fmaxf(c1, 0.f);
                c2 = fmaxf(c2, 0.f); c3 = fmaxf(c3, 0.f);
            }
            *(float2*)(Cmat + (size_t)r0 * C_ + col)       = make_float2(c0, c1);
            *(float2*)(Cmat + (size_t)(r0 + 8) * C_ + col) = make_float2(c2, c3);
        }
    }
}

// ==========================================================================
// Split all five weight matrices into bf16 hi/lo once.
// ==========================================================================
__global__ void k_split5(const float* __restrict__ w0, const float* __restrict__ w1,
                         const float* __restrict__ w2, const float* __restrict__ w3,
                         const float* __restrict__ w4,
                         __nv_bfloat16* __restrict__ hi, __nv_bfloat16* __restrict__ lo)
{
    size_t idx = (size_t)blockIdx.x * blockDim.x + threadIdx.x;   // < 5*WSZ_
    int sel = (int)(idx / WSZ_);
    size_t off = idx % WSZ_;
    const float* src = (sel == 0) ? w0 : (sel == 1) ? w1 : (sel == 2) ? w2 : (sel == 3) ? w3 : w4;
    float a = src[off];
    __nv_bfloat16 h = __float2bfloat16(a);
    hi[idx] = h;
    lo[idx] = __float2bfloat16(a - __bfloat162float(h));
}

// ==========================================================================
// Kernel 1: q-shift  ->  xx = shift(x) - x ;  xxx = x + xx * maa_x
// ==========================================================================
__global__ void k_shift(const float* __restrict__ x, const float* __restrict__ maa_x,
                        float* __restrict__ xx, float* __restrict__ xxx)
{
    int idx = blockIdx.x * blockDim.x + threadIdx.x;
    int c  = idx % C_;
    int bt = idx / C_;
    int t  = bt % T_;
    int w  = t % PW_;
    int h  = t / PW_;
    int quarter = (c & (HS_ - 1)) >> 4;

    float src = 0.f;
    if (quarter == 0)      { if (w > 0)       src = x[idx - C_]; }
    else if (quarter == 1) { if (w < PW_ - 1) src = x[idx + C_]; }
    else if (quarter == 2) { if (h > 0)       src = x[idx - PW_ * C_]; }
    else                   { if (h < PH_ - 1) src = x[idx + PW_ * C_]; }

    float xv = x[idx];
    float d  = src - xv;
    xx[idx]  = d;
    xxx[idx] = fmaf(d, maa_x[c], xv);
}

// ==========================================================================
// Pipelined tiled fp32 GEMM (small N/K GEMMs only)
// ==========================================================================
template<int EPI, bool BNT>
__global__ void __launch_bounds__(256, 2)
k_gemm(const float* __restrict__ A, const float* __restrict__ B,
       float* __restrict__ Cmat, int M, int N, int K, const float* __restrict__ bias)
{
    __shared__ float As[2][16][132];
    __shared__ float Bs[2][16][132];

    const int m0   = blockIdx.y * 128;
    const int n0   = blockIdx.x * 128;
    const int tid  = threadIdx.x;
    const int warp = tid >> 5;
    const int lane = tid & 31;
    const int tm   = (warp >> 2) * 64 + (lane >> 2) * 8;
    const int tn   = (warp & 3) * 32 + (lane & 3) * 8;

    float acc[8][8];
#pragma unroll
    for (int i = 0; i < 8; i++)
#pragma unroll
        for (int j = 0; j < 8; j++) acc[i][j] = 0.f;

    float4 aR[2], bR[2];

#define LDG_TILE(k0_)                                                          \
    {                                                                          \
        _Pragma("unroll")                                                      \
        for (int l = 0; l < 2; l++) {                                          \
            int e  = tid + l * 256;                                            \
            int am = e >> 2;                                                   \
            int ak = (e & 3) * 4;                                              \
            aR[l] = *(const float4*)(A + (size_t)(m0 + am) * K + (k0_) + ak);  \
            if (BNT) {                                                         \
                int bn = e >> 2;                                               \
                int bk = (e & 3) * 4;                                          \
                bR[l] = make_float4(0.f, 0.f, 0.f, 0.f);                       \
                if (n0 + bn < N)                                               \
                    bR[l] = *(const float4*)(B + (size_t)(n0 + bn) * K + (k0_) + bk); \
            } else {                                                           \
                int bk = e >> 5;                                               \
                int bn = (e & 31) * 4;                                         \
                bR[l] = make_float4(0.f, 0.f, 0.f, 0.f);                       \
                if (n0 + bn < N)                                               \
                    bR[l] = *(const float4*)(B + (size_t)((k0_) + bk) * N + n0 + bn); \
            }                                                                  \
        }                                                                      \
    }

#define STS_TILE(buf_)                                                         \
    {                                                                          \
        _Pragma("unroll")                                                      \
        for (int l = 0; l < 2; l++) {                                          \
            int e  = tid + l * 256;                                            \
            int am = e >> 2;                                                   \
            int ak = (e & 3) * 4;                                              \
            As[buf_][ak + 0][am] = aR[l].x; As[buf_][ak + 1][am] = aR[l].y;    \
            As[buf_][ak + 2][am] = aR[l].z; As[buf_][ak + 3][am] = aR[l].w;    \
            if (BNT) {                                                         \
                int bn = e >> 2;                                               \
                int bk = (e & 3) * 4;                                          \
                Bs[buf_][bk + 0][bn] = bR[l].x; Bs[buf_][bk + 1][bn] = bR[l].y;\
                Bs[buf_][bk + 2][bn] = bR[l].z; Bs[buf_][bk + 3][bn] = bR[l].w;\
            } else {                                                           \
                int bk = e >> 5;                                               \
                int bn = (e & 31) * 4;                                         \
                *(float4*)(&Bs[buf_][bk][bn]) = bR[l];                         \
            }                                                                  \
        }                                                                      \
    }

    LDG_TILE(0);
    STS_TILE(0);
    __syncthreads();

    int buf = 0;
    for (int k0 = 0; k0 < K; k0 += 16) {
        const bool hasNext = (k0 + 16 < K);
        if (hasNext) LDG_TILE(k0 + 16);

#pragma unroll
        for (int kk = 0; kk < 16; kk++) {
            float a[8], b[8];
            *(float4*)(a)     = *(const float4*)(&As[buf][kk][tm]);
            *(float4*)(a + 4) = *(const float4*)(&As[buf][kk][tm + 4]);
            *(float4*)(b)     = *(const float4*)(&Bs[buf][kk][tn]);
            *(float4*)(b + 4) = *(const float4*)(&Bs[buf][kk][tn + 4]);
#pragma unroll
            for (int i = 0; i < 8; i++)
#pragma unroll
                for (int j = 0; j < 8; j++)
                    acc[i][j] = fmaf(a[i], b[j], acc[i][j]);
        }

        if (hasNext) {
            STS_TILE(buf ^ 1);
            __syncthreads();
            buf ^= 1;
        }
    }
#undef LDG_TILE
#undef STS_TILE

#pragma unroll
    for (int i = 0; i < 8; i++) {
        int m = m0 + tm + i;
#pragma unroll
        for (int j = 0; j < 8; j++) {
            int n = n0 + tn + j;
            if (n < N) {
                float v = acc[i][j];
                if (EPI == 1) v = tanhf(v);
                else if (EPI == 2) v = fmaxf(v, 0.f);
                else if (EPI == 3) v = expf(-expf(bias[n] + v));
                Cmat[(size_t)m * N + n] = v;
            }
        }
    }
}

// ==========================================================================
// Kernel 3: token-mix; writes xw (fp32) + split bf16 pairs for xk,xv,xr,xg
// ==========================================================================
__global__ void __launch_bounds__(256)
k_mix(const float* __restrict__ x, const float* __restrict__ xx,
      const float* __restrict__ t5, const float* __restrict__ w2,
      const float* __restrict__ ma0, const float* __restrict__ ma1,
      const float* __restrict__ ma2, const float* __restrict__ ma3,
      const float* __restrict__ ma4,
      float* __restrict__ xw,
      __nv_bfloat16* __restrict__ acthi, __nv_bfloat16* __restrict__ actlo)
{
    const int r0  = blockIdx.x * 32;
    const int c0  = blockIdx.y * 128;
    const int tid = threadIdx.x;
    const int cl  = tid & 127;
    const int rh  = tid >> 7;

    __shared__ __align__(16) float tsh[32][36];
    __shared__ float wsh[32][128];

    const float* maas[5] = { ma0, ma1, ma2, ma3, ma4 };

    float xr_[16], xxr_[16];
#pragma unroll
    for (int kk = 0; kk < 16; kk++) {
        size_t idx = (size_t)(r0 + rh + 2 * kk) * C_ + c0 + cl;
        xr_[kk]  = x[idx];
        xxr_[kk] = xx[idx];
    }

#pragma unroll
    for (int f = 0; f < 5; f++) {
#pragma unroll
        for (int l = 0; l < 4; l++) {
            int e = tid + l * 256;
            tsh[e >> 5][e & 31] = t5[(size_t)(r0 + (e >> 5)) * 160 + f * 32 + (e & 31)];
        }
#pragma unroll
        for (int l = 0; l < 16; l++) {
            int e = tid + l * 256;
            wsh[e >> 7][e & 127] = w2[(size_t)(f * 32 + (e >> 7)) * C_ + c0 + (e & 127)];
        }
        __syncthreads();

        float wreg[32];
#pragma unroll
        for (int rr = 0; rr < 32; rr++) wreg[rr] = wsh[rr][cl];

        const float mf = maas[f][c0 + cl];
#pragma unroll
        for (int kk = 0; kk < 16; kk++) {
            const int row = rh + 2 * kk;
            const float4* trow = (const float4*)(&tsh[row][0]);
            float a = 0.f;
#pragma unroll
            for (int q = 0; q < 8; q++) {
                float4 t4 = trow[q];
                a = fmaf(t4.x, wreg[4 * q + 0], a);
                a = fmaf(t4.y, wreg[4 * q + 1], a);
                a = fmaf(t4.z, wreg[4 * q + 2], a);
                a = fmaf(t4.w, wreg[4 * q + 3], a);
            }
            size_t idx = (size_t)(r0 + row) * C_ + c0 + cl;
            float val = fmaf(xxr_[kk], mf + a, xr_[kk]);
            if (f == 0) {
                xw[idx] = val;
            } else {
                // slot (f-1): 0=k,1=v,2=r,3=g
                size_t o = (size_t)(f - 1) * NC_ + idx;
                __nv_bfloat16 h = __float2bfloat16(val);
                acthi[o] = h;
                actlo[o] = __float2bfloat16(val - __bfloat162float(h));
            }
        }
        __syncthreads();
    }
}

// ==========================================================================
// ruk[row,h] = sum_j r*u*k
// ==========================================================================
__global__ void k_ruk(const float* __restrict__ r, const float* __restrict__ k,
                      const float* __restrict__ u, float* __restrict__ ruk)
{
    const int row = blockIdx.x;
    const int c   = threadIdx.x;
    const int h   = c >> 6;
    const int j   = c & 63;
    size_t idx = (size_t)row * C_ + c;
    float p = r[idx] * u[c] * k[idx];
#pragma unroll
    for (int off = 16; off; off >>= 1) p += __shfl_xor_sync(0xffffffffu, p, off);
    __shared__ float ws[24];
    if ((c & 31) == 0) ws[c >> 5] = p;
    __syncthreads();
    if (j == 0) ruk[(size_t)row * H_ + h] = ws[2 * h] + ws[2 * h + 1];
}

// ==========================================================================
// WKV6 recurrence (256 threads, j split in quarters)
// ==========================================================================
__global__ void __launch_bounds__(256)
k_wkv(const float* __restrict__ r, const float* __restrict__ k,
      const float* __restrict__ v, const float* __restrict__ wd,
      const float* __restrict__ ruk, float* __restrict__ y)
{
    const int bh = blockIdx.x;
    const int b  = bh / H_;
    const int h  = bh % H_;
    const int tid = threadIdx.x;
    const int i  = tid & 63;
    const int q  = tid >> 6;

    __shared__ __align__(16) float sr[64];
    __shared__ __align__(16) float sk[64];
    __shared__ __align__(16) float sw[64];
    __shared__ __align__(16) float sv[64];
    __shared__ float part[3][64];

    float S[16];
#pragma unroll
    for (int jj = 0; jj < 16; jj++) S[jj] = 0.f;

    const size_t base  = (size_t)b * T_ * C_ + h * 64;
    const size_t rbase = (size_t)b * T_ * H_ + h;

    const float* mysrc = (q == 0) ? r : (q == 1) ? k : (q == 2) ? wd : v;
    float cur = mysrc[base + i];

    for (int t = 0; t < T_; t++) {
        if (q == 0)      sr[i] = cur;
        else if (q == 1) sk[i] = cur;
        else if (q == 2) sw[i] = cur;
        else             sv[i] = cur;
        __syncthreads();

        float nxt = cur;
        if (t + 1 < T_) nxt = mysrc[base + (size_t)(t + 1) * C_ + i];

        const float vi = sv[i];
        float yp = 0.f;
#pragma unroll
        for (int g4 = 0; g4 < 4; g4++) {
            float4 r4 = *(const float4*)(sr + q * 16 + g4 * 4);
            float4 k4 = *(const float4*)(sk + q * 16 + g4 * 4);
            float4 w4 = *(const float4*)(sw + q * 16 + g4 * 4);
            float kv;
            kv = k4.x * vi; yp = fmaf(r4.x, S[4*g4+0], yp); S[4*g4+0] = fmaf(w4.x, S[4*g4+0], kv);
            kv = k4.y * vi; yp = fmaf(r4.y, S[4*g4+1], yp); S[4*g4+1] = fmaf(w4.y, S[4*g4+1], kv);
            kv = k4.z * vi; yp = fmaf(r4.z, S[4*g4+2], yp); S[4*g4+2] = fmaf(w4.z, S[4*g4+2], kv);
            kv = k4.w * vi; yp = fmaf(r4.w, S[4*g4+3], yp); S[4*g4+3] = fmaf(w4.w, S[4*g4+3], kv);
        }
        if (q) part[q - 1][i] = yp;
        __syncthreads();

        if (q == 0) {
            float yv = yp + part[0][i] + part[1][i] + part[2][i];
            yv = fmaf(ruk[rbase + (size_t)t * H_], vi, yv);
            y[base + (size_t)t * C_ + i] = yv;
        }
        cur = nxt;
    }
}

// ==========================================================================
// GroupNorm * g  -> bf16 hi/lo split directly (for the W_o GEMM)
// ==========================================================================
__global__ void k_gnorm(const float* __restrict__ y, const float* __restrict__ gbuf,
                        const float* __restrict__ lnw, const float* __restrict__ lnb,
                        __nv_bfloat16* __restrict__ hi, __nv_bfloat16* __restrict__ lo)
{
    const int row = blockIdx.x;
    const int c   = threadIdx.x;
    size_t idx = (size_t)row * C_ + c;
    float v = y[idx];
    float s = v, s2 = v * v;
#pragma unroll
    for (int off = 16; off; off >>= 1) {
        s  += __shfl_xor_sync(0xffffffffu, s,  off);
        s2 += __shfl_xor_sync(0xffffffffu, s2, off);
    }
    __shared__ float as[24], as2[24];
    if ((c & 31) == 0) { as[c >> 5] = s; as2[c >> 5] = s2; }
    __syncthreads();
    const int g = c >> 6;
    float sum  = as[2 * g]  + as[2 * g + 1];
    float sum2 = as2[2 * g] + as2[2 * g + 1];
    float mu   = sum * (1.f / 64.f);
    float var  = sum2 * (1.f / 64.f) - mu * mu;
    float nv   = (v - mu) * rsqrtf(var + 1e-5f);
    float val  = fmaf(nv, lnw[c], lnb[c]) * gbuf[idx];
    __nv_bfloat16 h = __float2bfloat16(val);
    hi[idx] = h;
    lo[idx] = __float2bfloat16(val - __bfloat162float(h));
}

// ==========================================================================
// Host launcher
// ==========================================================================
extern "C" void kernel_launch(void* const* d_in, const int* in_sizes, int n_in,
                              void* d_out, int out_size)
{
    const float* x     = (const float*)d_in[0];
    const float* W_r   = (const float*)d_in[1];
    const float* W_k   = (const float*)d_in[2];
    const float* W_v   = (const float*)d_in[3];
    const float* W_g   = (const float*)d_in[4];
    const float* W_o   = (const float*)d_in[5];
    const float* maa_x = (const float*)d_in[6];
    const float* maa_w = (const float*)d_in[7];
    const float* maa_k = (const float*)d_in[8];
    const float* maa_v = (const float*)d_in[9];
    const float* maa_r = (const float*)d_in[10];
    const float* maa_g = (const float*)d_in[11];
    const float* maa_w1= (const float*)d_in[12];
    const float* maa_w2= (const float*)d_in[13];
    const float* tdec  = (const float*)d_in[14];
    const float* dec_w1= (const float*)d_in[15];
    const float* dec_w2= (const float*)d_in[16];
    const float* faaaa = (const float*)d_in[17];
    const float* ln_w  = (const float*)d_in[18];
    const float* ln_b  = (const float*)d_in[19];
    (void)in_sizes; (void)n_in; (void)out_size;

    float* S = nullptr;
    cudaGetSymbolAddress((void**)&S, g_scratch);
    __nv_bfloat16 *acthi = nullptr, *actlo = nullptr, *w5hi = nullptr, *w5lo = nullptr;
    cudaGetSymbolAddress((void**)&acthi, g_acthi);
    cudaGetSymbolAddress((void**)&actlo, g_actlo);
    cudaGetSymbolAddress((void**)&w5hi, g_w5hi);
    cudaGetSymbolAddress((void**)&w5lo, g_w5lo);

    static bool attr_done = false;
    if (!attr_done) {
        cudaFuncSetAttribute(k_gemm_mma, cudaFuncAttributeMaxDynamicSharedMemorySize, SMEM_MMA);
        attr_done = true;
    }

    float* xx   = S + OFF_XX;
    float* xxx  = S + OFF_XXX;
    float* t5   = S + OFF_T5;
    float* xw   = S + OFF_XW;
    float* rb   = S + OFF_R;
    float* kb   = S + OFF_K;
    float* vb   = S + OFF_V;
    float* gb   = S + OFF_G;
    float* h1   = S + OFF_H1;
    float* wdec = S + OFF_WDEC;
    float* yb   = S + OFF_Y;
    float* ruk  = S + OFF_RUK;
    float* outp = (float*)d_out;

    const dim3 gTC(C_ / 128, NR_ / 128);   // (6, 64)

    // 0. split all 5 weights (independent)
    k_split5<<<(unsigned)(5 * WSZ_ / 256), 256>>>(W_r, W_k, W_v, W_g, W_o, w5hi, w5lo);

    // 1. shift + xxx
    k_shift<<<(unsigned)(NC_ / 256), 256>>>(x, maa_x, xx, xxx);

    // 2. t5 = tanh(xxx @ maa_w1)
    k_gemm<1, false><<<dim3(2, NR_ / 128), 256>>>(xxx, maa_w1, t5, NR_, 160, C_, nullptr);

    // 3. token mix -> xw fp32 + bf16 pairs for k,v,r,g
    k_mix<<<dim3(NR_ / 32, C_ / 128), 256>>>(x, xx, t5, maa_w2,
                                             maa_w, maa_k, maa_v, maa_r, maa_g,
                                             xw, acthi, actlo);

    // 4. big NT GEMMs (bf16-split mma.sync). act slots: 0=k,1=v,2=r,3=g
    k_gemm_mma<<<gTC, 256, SMEM_MMA>>>(acthi + 2 * NC_, actlo + 2 * NC_,
                                       w5hi + 0 * WSZ_, w5lo + 0 * WSZ_, rb, 0);
    k_gemm_mma<<<gTC, 256, SMEM_MMA>>>(acthi + 0 * NC_, actlo + 0 * NC_,
                                       w5hi + 1 * WSZ_, w5lo + 1 * WSZ_, kb, 0);
    k_gemm_mma<<<gTC, 256, SMEM_MMA>>>(acthi + 1 * NC_, actlo + 1 * NC_,
                                       w5hi + 2 * WSZ_, w5lo + 2 * WSZ_, vb, 0);
    k_gemm_mma<<<gTC, 256, SMEM_MMA>>>(acthi + 3 * NC_, actlo + 3 * NC_,
                                       w5hi + 3 * WSZ_, w5lo + 3 * WSZ_, gb, 1);  // relu

    // 5. decay path (small fp32 GEMMs)
    k_gemm<1, false><<<dim3(1, NR_ / 128), 256>>>(xw, dec_w1, h1, NR_, 64, C_, nullptr);
    k_gemm<3, false><<<dim3(C_ / 128, NR_ / 128), 256>>>(h1, dec_w2, wdec, NR_, C_, 64, tdec);

    // 6. wkv recurrence
    k_ruk<<<NR_, C_>>>(rb, kb, faaaa, ruk);
    k_wkv<<<B_ * H_, 256>>>(rb, kb, vb, wdec, ruk, yb);

    // 7. groupnorm * g -> bf16 pair (reuse act slot 0)
    k_gnorm<<<NR_, C_>>>(yb, gb, ln_w, ln_b, acthi, actlo);

    // 8. out = yn @ W_o^T
    k_gemm_mma<<<gTC, 256, SMEM_MMA>>>(acthi, actlo,
                                       w5hi + 4 * WSZ_, w5lo + 4 * WSZ_, outp, 0);
}

// round 7
// speedup vs baseline: 1.0680x; 1.0680x over previous
#include <cuda_runtime.h>
#include <cuda_bf16.h>
#include <math.h>
#include <stdint.h>

// ---------------- problem constants (fixed shapes) ----------------
#define B_   8
#define T_   1024
#define C_   768
#define H_   12
#define HS_  64
#define PH_  32
#define PW_  32
#define NR_  (B_ * T_)          // 8192 rows
#define NC_  ((size_t)NR_ * C_) // 6291456 elems
#define WSZ_ ((size_t)C_ * C_)  // 589824

// ---------------- scratch ----------------
// NOTE: xk,xv,xr,xg are contiguous so k_split4 can treat them as one array.
__device__ __align__(16) float g_scratch[14 * NC_ + (size_t)NR_ * 160 + (size_t)NR_ * 64 + (size_t)NR_ * H_];
__device__ __align__(16) __nv_bfloat16 g_acthi[4 * NC_];   // slots: 0=k,1=v,2=r,3=g
__device__ __align__(16) __nv_bfloat16 g_actlo[4 * NC_];
__device__ __align__(16) __nv_bfloat16 g_w5hi[5 * WSZ_];   // W_r,W_k,W_v,W_g,W_o
__device__ __align__(16) __nv_bfloat16 g_w5lo[5 * WSZ_];

#define OFF_XX   ((size_t)0)
#define OFF_XXX  (OFF_XX  + NC_)
#define OFF_T5   (OFF_XXX + NC_)
#define OFF_XW   (OFF_T5  + (size_t)NR_ * 160)
#define OFF_XK   (OFF_XW  + NC_)       // k,v,r,g contiguous (4*NC_)
#define OFF_XV   (OFF_XK  + NC_)
#define OFF_XR   (OFF_XV  + NC_)
#define OFF_XG   (OFF_XR  + NC_)
#define OFF_R    (OFF_XG  + NC_)
#define OFF_K    (OFF_R   + NC_)
#define OFF_V    (OFF_K   + NC_)
#define OFF_G    (OFF_V   + NC_)
#define OFF_H1   (OFF_G   + NC_)
#define OFF_WDEC (OFF_H1  + (size_t)NR_ * 64)
#define OFF_Y    (OFF_WDEC+ NC_)
#define OFF_RUK  (OFF_Y   + NC_)

// ========================= helpers ==========================
__device__ __forceinline__ uint32_t smem_u32(const void* p) {
    uint32_t a;
    asm("{ .reg .u64 t; cvta.to.shared.u64 t, %1; cvt.u32.u64 %0, t; }" : "=r"(a) : "l"(p));
    return a;
}
__device__ __forceinline__ void ldsm_x4(uint32_t* r, uint32_t addr) {
    asm volatile("ldmatrix.sync.aligned.m8n8.x4.shared.b16 {%0,%1,%2,%3}, [%4];"
                 : "=r"(r[0]), "=r"(r[1]), "=r"(r[2]), "=r"(r[3]) : "r"(addr));
}
__device__ __forceinline__ void mma_bf16(float* c, const uint32_t* a, uint32_t b0, uint32_t b1) {
    asm volatile("mma.sync.aligned.m16n8k16.row.col.f32.bf16.bf16.f32 "
                 "{%0,%1,%2,%3}, {%4,%5,%6,%7}, {%8,%9}, {%0,%1,%2,%3};"
                 : "+f"(c[0]), "+f"(c[1]), "+f"(c[2]), "+f"(c[3])
                 : "r"(a[0]), "r"(a[1]), "r"(a[2]), "r"(a[3]), "r"(b0), "r"(b1));
}

// ==========================================================================
// bf16-split tensor-core GEMM via mma.sync (R5 proven version):
//   C[8192,768] = epi( A[8192,768] @ W[768,768]^T )
//   D = Ahi*Whi + Alo*Whi + Ahi*Wlo  (virtual K' = 2304 = 72 tiles of K32)
// Block 128x128, 256 thr (8 warps 2x4, warp tile 64x32), double-buffered.
// ==========================================================================
#define PLANE_   2080
#define ATILE_   (4 * PLANE_)           // 8320
#define BUFSZ_   (2 * ATILE_)           // 16640

__global__ void __launch_bounds__(256, 2)
k_gemm_mma(const __nv_bfloat16* __restrict__ Ahi, const __nv_bfloat16* __restrict__ Alo,
           const __nv_bfloat16* __restrict__ Whi, const __nv_bfloat16* __restrict__ Wlo,
           float* __restrict__ Cmat, int doRelu)
{
    __shared__ __align__(16) char sm[2][BUFSZ_];

    const int tid  = threadIdx.x;
    const int warp = tid >> 5;
    const int lane = tid & 31;
    const int m0 = blockIdx.y * 128;
    const int n0 = blockIdx.x * 128;
    const int wm = warp >> 2;
    const int wn = warp & 3;

    float acc[4][4][4];
#pragma unroll
    for (int i = 0; i < 4; i++)
#pragma unroll
        for (int j = 0; j < 4; j++)
#pragma unroll
            for (int q = 0; q < 4; q++) acc[i][j][q] = 0.f;

    const int ldrow = tid >> 1;
    const int ldcb  = (tid & 1) * 2;

    uint4 ra[2], rb[2];

    const uint32_t sb = smem_u32(sm);
    const int lgrp = lane >> 3;
    const int lrl  = lane & 7;

#define LDG_T(c_)                                                               \
    {                                                                           \
        const int seg_ = (c_) / 24;                                             \
        const int kc_  = ((c_) % 24) * 32;                                      \
        const __nv_bfloat16* Ag = (seg_ == 1) ? Alo : Ahi;                      \
        const __nv_bfloat16* Bg = (seg_ == 2) ? Wlo : Whi;                      \
        const __nv_bfloat16* ap = Ag + (size_t)(m0 + ldrow) * C_ + kc_ + ldcb * 8; \
        const __nv_bfloat16* bp = Bg + (size_t)(n0 + ldrow) * C_ + kc_ + ldcb * 8; \
        ra[0] = *(const uint4*)ap; ra[1] = *(const uint4*)(ap + 8);             \
        rb[0] = *(const uint4*)bp; rb[1] = *(const uint4*)(bp + 8);             \
    }

#define STS_T(buf_)                                                             \
    {                                                                           \
        char* b_ = sm[buf_];                                                    \
        *(uint4*)(b_ + (ldcb + 0) * PLANE_ + ldrow * 16) = ra[0];               \
        *(uint4*)(b_ + (ldcb + 1) * PLANE_ + ldrow * 16) = ra[1];               \
        *(uint4*)(b_ + ATILE_ + (ldcb + 0) * PLANE_ + ldrow * 16) = rb[0];      \
        *(uint4*)(b_ + ATILE_ + (ldcb + 1) * PLANE_ + ldrow * 16) = rb[1];      \
    }

    LDG_T(0);
    STS_T(0);
    __syncthreads();

    for (int c = 0; c < 72; c++) {
        const int buf = c & 1;
        const bool hasNext = (c + 1 < 72);
        if (hasNext) LDG_T(c + 1);

        const uint32_t abase = sb + buf * BUFSZ_;
        const uint32_t bbase = abase + ATILE_;

#pragma unroll
        for (int kk = 0; kk < 2; kk++) {
            uint32_t afr[4][4], bfr[2][4];
#pragma unroll
            for (int mt = 0; mt < 4; mt++) {
                int row   = wm * 64 + mt * 16 + (lgrp & 1) * 8 + lrl;
                int chunk = kk * 2 + (lgrp >> 1);
                ldsm_x4(afr[mt], abase + chunk * PLANE_ + row * 16);
            }
#pragma unroll
            for (int nt = 0; nt < 2; nt++) {
                int nr    = wn * 32 + nt * 16 + (lgrp >> 1) * 8 + lrl;
                int chunk = kk * 2 + (lgrp & 1);
                ldsm_x4(bfr[nt], bbase + chunk * PLANE_ + nr * 16);
            }
#pragma unroll
            for (int mt = 0; mt < 4; mt++)
#pragma unroll
                for (int ng = 0; ng < 4; ng++)
                    mma_bf16(acc[mt][ng], afr[mt], bfr[ng >> 1][(ng & 1) * 2 + 0],
                             bfr[ng >> 1][(ng & 1) * 2 + 1]);
        }

        if (hasNext) {
            STS_T(buf ^ 1);
            __syncthreads();
        }
    }
#undef LDG_T
#undef STS_T

#pragma unroll
    for (int mt = 0; mt < 4; mt++) {
        const int r0 = m0 + wm * 64 + mt * 16 + (lane >> 2);
#pragma unroll
        for (int ng = 0; ng < 4; ng++) {
            const int col = n0 + wn * 32 + ng * 8 + (lane & 3) * 2;
            float c0 = acc[mt][ng][0], c1 = acc[mt][ng][1];
            float c2 = acc[mt][ng][2], c3 = acc[mt][ng][3];
            if (doRelu) {
                c0 = fmaxf(c0, 0.f); c1 = fmaxf(c1, 0.f);
                c2 = fmaxf(c2, 0.f); c3 = fmaxf(c3, 0.f);
            }
            *(float2*)(Cmat + (size_t)r0 * C_ + col)       = make_float2(c0, c1);
            *(float2*)(Cmat + (size_t)(r0 + 8) * C_ + col) = make_float2(c2, c3);
        }
    }
}

// ==========================================================================
// Split all five weight matrices into bf16 hi/lo once.
// ==========================================================================
__global__ void k_split5(const float* __restrict__ w0, const float* __restrict__ w1,
                         const float* __restrict__ w2, const float* __restrict__ w3,
                         const float* __restrict__ w4,
                         __nv_bfloat16* __restrict__ hi, __nv_bfloat16* __restrict__ lo)
{
    size_t idx = (size_t)blockIdx.x * blockDim.x + threadIdx.x;   // < 5*WSZ_
    int sel = (int)(idx / WSZ_);
    size_t off = idx % WSZ_;
    const float* src = (sel == 0) ? w0 : (sel == 1) ? w1 : (sel == 2) ? w2 : (sel == 3) ? w3 : w4;
    float a = src[off];
    __nv_bfloat16 h = __float2bfloat16(a);
    hi[idx] = h;
    lo[idx] = __float2bfloat16(a - __bfloat162float(h));
}

// ==========================================================================
// Batched activation split: in = 4 contiguous [NR_,C_] fp32 buffers (k,v,r,g)
// float4 vectorized; each thread handles 4 elements.
// ==========================================================================
__global__ void __launch_bounds__(256)
k_split4(const float* __restrict__ in, __nv_bfloat16* __restrict__ hi,
         __nv_bfloat16* __restrict__ lo)
{
    size_t i4 = (size_t)blockIdx.x * blockDim.x + threadIdx.x;   // float4 id < NC_
    float4 a = *(const float4*)(in + i4 * 4);
    __nv_bfloat16 h0 = __float2bfloat16(a.x);
    __nv_bfloat16 h1 = __float2bfloat16(a.y);
    __nv_bfloat16 h2 = __float2bfloat16(a.z);
    __nv_bfloat16 h3 = __float2bfloat16(a.w);
    __nv_bfloat162 hp0, hp1, lp0, lp1;
    hp0.x = h0; hp0.y = h1; hp1.x = h2; hp1.y = h3;
    lp0.x = __float2bfloat16(a.x - __bfloat162float(h0));
    lp0.y = __float2bfloat16(a.y - __bfloat162float(h1));
    lp1.x = __float2bfloat16(a.z - __bfloat162float(h2));
    lp1.y = __float2bfloat16(a.w - __bfloat162float(h3));
    *(uint2*)(hi + i4 * 4) = make_uint2(*(uint32_t*)&hp0, *(uint32_t*)&hp1);
    *(uint2*)(lo + i4 * 4) = make_uint2(*(uint32_t*)&lp0, *(uint32_t*)&lp1);
}

// ==========================================================================
// Kernel 1: q-shift  ->  xx = shift(x) - x ;  xxx = x + xx * maa_x
// ==========================================================================
__global__ void k_shift(const float* __restrict__ x, const float* __restrict__ maa_x,
                        float* __restrict__ xx, float* __restrict__ xxx)
{
    int idx = blockIdx.x * blockDim.x + threadIdx.x;
    int c  = idx % C_;
    int bt = idx / C_;
    int t  = bt % T_;
    int w  = t % PW_;
    int h  = t / PW_;
    int quarter = (c & (HS_ - 1)) >> 4;

    float src = 0.f;
    if (quarter == 0)      { if (w > 0)       src = x[idx - C_]; }
    else if (quarter == 1) { if (w < PW_ - 1) src = x[idx + C_]; }
    else if (quarter == 2) { if (h > 0)       src = x[idx - PW_ * C_]; }
    else                   { if (h < PH_ - 1) src = x[idx + PW_ * C_]; }

    float xv = x[idx];
    float d  = src - xv;
    xx[idx]  = d;
    xxx[idx] = fmaf(d, maa_x[c], xv);
}

// ==========================================================================
// Pipelined tiled fp32 GEMM (small N/K GEMMs only)
// ==========================================================================
template<int EPI, bool BNT>
__global__ void __launch_bounds__(256, 2)
k_gemm(const float* __restrict__ A, const float* __restrict__ B,
       float* __restrict__ Cmat, int M, int N, int K, const float* __restrict__ bias)
{
    __shared__ float As[2][16][132];
    __shared__ float Bs[2][16][132];

    const int m0   = blockIdx.y * 128;
    const int n0   = blockIdx.x * 128;
    const int tid  = threadIdx.x;
    const int warp = tid >> 5;
    const int lane = tid & 31;
    const int tm   = (warp >> 2) * 64 + (lane >> 2) * 8;
    const int tn   = (warp & 3) * 32 + (lane & 3) * 8;

    float acc[8][8];
#pragma unroll
    for (int i = 0; i < 8; i++)
#pragma unroll
        for (int j = 0; j < 8; j++) acc[i][j] = 0.f;

    float4 aR[2], bR[2];

#define LDG_TILE(k0_)                                                          \
    {                                                                          \
        _Pragma("unroll")                                                      \
        for (int l = 0; l < 2; l++) {                                          \
            int e  = tid + l * 256;                                            \
            int am = e >> 2;                                                   \
            int ak = (e & 3) * 4;                                              \
            aR[l] = *(const float4*)(A + (size_t)(m0 + am) * K + (k0_) + ak);  \
            if (BNT) {                                                         \
                int bn = e >> 2;                                               \
                int bk = (e & 3) * 4;                                          \
                bR[l] = make_float4(0.f, 0.f, 0.f, 0.f);                       \
                if (n0 + bn < N)                                               \
                    bR[l] = *(const float4*)(B + (size_t)(n0 + bn) * K + (k0_) + bk); \
            } else {                                                           \
                int bk = e >> 5;                                               \
                int bn = (e & 31) * 4;                                         \
                bR[l] = make_float4(0.f, 0.f, 0.f, 0.f);                       \
                if (n0 + bn < N)                                               \
                    bR[l] = *(const float4*)(B + (size_t)((k0_) + bk) * N + n0 + bn); \
            }                                                                  \
        }                                                                      \
    }

#define STS_TILE(buf_)                                                         \
    {                                                                          \
        _Pragma("unroll")                                                      \
        for (int l = 0; l < 2; l++) {                                          \
            int e  = tid + l * 256;                                            \
            int am = e >> 2;                                                   \
            int ak = (e & 3) * 4;                                              \
            As[buf_][ak + 0][am] = aR[l].x; As[buf_][ak + 1][am] = aR[l].y;    \
            As[buf_][ak + 2][am] = aR[l].z; As[buf_][ak + 3][am] = aR[l].w;    \
            if (BNT) {                                                         \
                int bn = e >> 2;                                               \
                int bk = (e & 3) * 4;                                          \
                Bs[buf_][bk + 0][bn] = bR[l].x; Bs[buf_][bk + 1][bn] = bR[l].y;\
                Bs[buf_][bk + 2][bn] = bR[l].z; Bs[buf_][bk + 3][bn] = bR[l].w;\
            } else {                                                           \
                int bk = e >> 5;                                               \
                int bn = (e & 31) * 4;                                         \
                *(float4*)(&Bs[buf_][bk][bn]) = bR[l];                         \
            }                                                                  \
        }                                                                      \
    }

    LDG_TILE(0);
    STS_TILE(0);
    __syncthreads();

    int buf = 0;
    for (int k0 = 0; k0 < K; k0 += 16) {
        const bool hasNext = (k0 + 16 < K);
        if (hasNext) LDG_TILE(k0 + 16);

#pragma unroll
        for (int kk = 0; kk < 16; kk++) {
            float a[8], b[8];
            *(float4*)(a)     = *(const float4*)(&As[buf][kk][tm]);
            *(float4*)(a + 4) = *(const float4*)(&As[buf][kk][tm + 4]);
            *(float4*)(b)     = *(const float4*)(&Bs[buf][kk][tn]);
            *(float4*)(b + 4) = *(const float4*)(&Bs[buf][kk][tn + 4]);
#pragma unroll
            for (int i = 0; i < 8; i++)
#pragma unroll
                for (int j = 0; j < 8; j++)
                    acc[i][j] = fmaf(a[i], b[j], acc[i][j]);
        }

        if (hasNext) {
            STS_TILE(buf ^ 1);
            __syncthreads();
            buf ^= 1;
        }
    }
#undef LDG_TILE
#undef STS_TILE

#pragma unroll
    for (int i = 0; i < 8; i++) {
        int m = m0 + tm + i;
#pragma unroll
        for (int j = 0; j < 8; j++) {
            int n = n0 + tn + j;
            if (n < N) {
                float v = acc[i][j];
                if (EPI == 1) v = tanhf(v);
                else if (EPI == 2) v = fmaxf(v, 0.f);
                else if (EPI == 3) v = expf(-expf(bias[n] + v));
                Cmat[(size_t)m * N + n] = v;
            }
        }
    }
}

// ==========================================================================
// Kernel 3: token-mix (R5 version: five fp32 outputs)
// ==========================================================================
__global__ void __launch_bounds__(256)
k_mix(const float* __restrict__ x, const float* __restrict__ xx,
      const float* __restrict__ t5, const float* __restrict__ w2,
      const float* __restrict__ ma0, const float* __restrict__ ma1,
      const float* __restrict__ ma2, const float* __restrict__ ma3,
      const float* __restrict__ ma4,
      float* __restrict__ o0, float* __restrict__ o1, float* __restrict__ o2,
      float* __restrict__ o3, float* __restrict__ o4)
{
    const int r0  = blockIdx.x * 32;
    const int c0  = blockIdx.y * 128;
    const int tid = threadIdx.x;
    const int cl  = tid & 127;
    const int rh  = tid >> 7;

    __shared__ __align__(16) float tsh[32][36];
    __shared__ float wsh[32][128];

    const float* maas[5] = { ma0, ma1, ma2, ma3, ma4 };
    float*       outs[5] = { o0, o1, o2, o3, o4 };

    float xr_[16], xxr_[16];
#pragma unroll
    for (int kk = 0; kk < 16; kk++) {
        size_t idx = (size_t)(r0 + rh + 2 * kk) * C_ + c0 + cl;
        xr_[kk]  = x[idx];
        xxr_[kk] = xx[idx];
    }

#pragma unroll
    for (int f = 0; f < 5; f++) {
#pragma unroll
        for (int l = 0; l < 4; l++) {
            int e = tid + l * 256;
            tsh[e >> 5][e & 31] = t5[(size_t)(r0 + (e >> 5)) * 160 + f * 32 + (e & 31)];
        }
#pragma unroll
        for (int l = 0; l < 16; l++) {
            int e = tid + l * 256;
            wsh[e >> 7][e & 127] = w2[(size_t)(f * 32 + (e >> 7)) * C_ + c0 + (e & 127)];
        }
        __syncthreads();

        float wreg[32];
#pragma unroll
        for (int rr = 0; rr < 32; rr++) wreg[rr] = wsh[rr][cl];

        const float mf = maas[f][c0 + cl];
        float* const outp = outs[f];
#pragma unroll
        for (int kk = 0; kk < 16; kk++) {
            const int row = rh + 2 * kk;
            const float4* trow = (const float4*)(&tsh[row][0]);
            float a = 0.f;
#pragma unroll
            for (int q = 0; q < 8; q++) {
                float4 t4 = trow[q];
                a = fmaf(t4.x, wreg[4 * q + 0], a);
                a = fmaf(t4.y, wreg[4 * q + 1], a);
                a = fmaf(t4.z, wreg[4 * q + 2], a);
                a = fmaf(t4.w, wreg[4 * q + 3], a);
            }
            size_t idx = (size_t)(r0 + row) * C_ + c0 + cl;
            outp[idx] = fmaf(xxr_[kk], mf + a, xr_[kk]);
        }
        __syncthreads();
    }
}

// ==========================================================================
// ruk[row,h] = sum_j r*u*k
// ==========================================================================
__global__ void k_ruk(const float* __restrict__ r, const float* __restrict__ k,
                      const float* __restrict__ u, float* __restrict__ ruk)
{
    const int row = blockIdx.x;
    const int c   = threadIdx.x;
    const int h   = c >> 6;
    const int j   = c & 63;
    size_t idx = (size_t)row * C_ + c;
    float p = r[idx] * u[c] * k[idx];
#pragma unroll
    for (int off = 16; off; off >>= 1) p += __shfl_xor_sync(0xffffffffu, p, off);
    __shared__ float ws[24];
    if ((c & 31) == 0) ws[c >> 5] = p;
    __syncthreads();
    if (j == 0) ruk[(size_t)row * H_ + h] = ws[2 * h] + ws[2 * h + 1];
}

// ==========================================================================
// WKV6 recurrence (256 threads, j split in quarters)
// ==========================================================================
__global__ void __launch_bounds__(256)
k_wkv(const float* __restrict__ r, const float* __restrict__ k,
      const float* __restrict__ v, const float* __restrict__ wd,
      const float* __restrict__ ruk, float* __restrict__ y)
{
    const int bh = blockIdx.x;
    const int b  = bh / H_;
    const int h  = bh % H_;
    const int tid = threadIdx.x;
    const int i  = tid & 63;
    const int q  = tid >> 6;

    __shared__ __align__(16) float sr[64];
    __shared__ __align__(16) float sk[64];
    __shared__ __align__(16) float sw[64];
    __shared__ __align__(16) float sv[64];
    __shared__ float part[3][64];

    float S[16];
#pragma unroll
    for (int jj = 0; jj < 16; jj++) S[jj] = 0.f;

    const size_t base  = (size_t)b * T_ * C_ + h * 64;
    const size_t rbase = (size_t)b * T_ * H_ + h;

    const float* mysrc = (q == 0) ? r : (q == 1) ? k : (q == 2) ? wd : v;
    float cur = mysrc[base + i];

    for (int t = 0; t < T_; t++) {
        if (q == 0)      sr[i] = cur;
        else if (q == 1) sk[i] = cur;
        else if (q == 2) sw[i] = cur;
        else             sv[i] = cur;
        __syncthreads();

        float nxt = cur;
        if (t + 1 < T_) nxt = mysrc[base + (size_t)(t + 1) * C_ + i];

        const float vi = sv[i];
        float yp = 0.f;
#pragma unroll
        for (int g4 = 0; g4 < 4; g4++) {
            float4 r4 = *(const float4*)(sr + q * 16 + g4 * 4);
            float4 k4 = *(const float4*)(sk + q * 16 + g4 * 4);
            float4 w4 = *(const float4*)(sw + q * 16 + g4 * 4);
            float kv;
            kv = k4.x * vi; yp = fmaf(r4.x, S[4*g4+0], yp); S[4*g4+0] = fmaf(w4.x, S[4*g4+0], kv);
            kv = k4.y * vi; yp = fmaf(r4.y, S[4*g4+1], yp); S[4*g4+1] = fmaf(w4.y, S[4*g4+1], kv);
            kv = k4.z * vi; yp = fmaf(r4.z, S[4*g4+2], yp); S[4*g4+2] = fmaf(w4.z, S[4*g4+2], kv);
            kv = k4.w * vi; yp = fmaf(r4.w, S[4*g4+3], yp); S[4*g4+3] = fmaf(w4.w, S[4*g4+3], kv);
        }
        if (q) part[q - 1][i] = yp;
        __syncthreads();

        if (q == 0) {
            float yv = yp + part[0][i] + part[1][i] + part[2][i];
            yv = fmaf(ruk[rbase + (size_t)t * H_], vi, yv);
            y[base + (size_t)t * C_ + i] = yv;
        }
        cur = nxt;
    }
}

// ==========================================================================
// GroupNorm * g  -> bf16 hi/lo split directly (for the W_o GEMM)
// ==========================================================================
__global__ void k_gnorm(const float* __restrict__ y, const float* __restrict__ gbuf,
                        const float* __restrict__ lnw, const float* __restrict__ lnb,
                        __nv_bfloat16* __restrict__ hi, __nv_bfloat16* __restrict__ lo)
{
    const int row = blockIdx.x;
    const int c   = threadIdx.x;
    size_t idx = (size_t)row * C_ + c;
    float v = y[idx];
    float s = v, s2 = v * v;
#pragma unroll
    for (int off = 16; off; off >>= 1) {
        s  += __shfl_xor_sync(0xffffffffu, s,  off);
        s2 += __shfl_xor_sync(0xffffffffu, s2, off);
    }
    __shared__ float as[24], as2[24];
    if ((c & 31) == 0) { as[c >> 5] = s; as2[c >> 5] = s2; }
    __syncthreads();
    const int g = c >> 6;
    float sum  = as[2 * g]  + as[2 * g + 1];
    float sum2 = as2[2 * g] + as2[2 * g + 1];
    float mu   = sum * (1.f / 64.f);
    float var  = sum2 * (1.f / 64.f) - mu * mu;
    float nv   = (v - mu) * rsqrtf(var + 1e-5f);
    float val  = fmaf(nv, lnw[c], lnb[c]) * gbuf[idx];
    __nv_bfloat16 h = __float2bfloat16(val);
    hi[idx] = h;
    lo[idx] = __float2bfloat16(val - __bfloat162float(h));
}

// ==========================================================================
// Host launcher
// ==========================================================================
extern "C" void kernel_launch(void* const* d_in, const int* in_sizes, int n_in,
                              void* d_out, int out_size)
{
    const float* x     = (const float*)d_in[0];
    const float* W_r   = (const float*)d_in[1];
    const float* W_k   = (const float*)d_in[2];
    const float* W_v   = (const float*)d_in[3];
    const float* W_g   = (const float*)d_in[4];
    const float* W_o   = (const float*)d_in[5];
    const float* maa_x = (const float*)d_in[6];
    const float* maa_w = (const float*)d_in[7];
    const float* maa_k = (const float*)d_in[8];
    const float* maa_v = (const float*)d_in[9];
    const float* maa_r = (const float*)d_in[10];
    const float* maa_g = (const float*)d_in[11];
    const float* maa_w1= (const float*)d_in[12];
    const float* maa_w2= (const float*)d_in[13];
    const float* tdec  = (const float*)d_in[14];
    const float* dec_w1= (const float*)d_in[15];
    const float* dec_w2= (const float*)d_in[16];
    const float* faaaa = (const float*)d_in[17];
    const float* ln_w  = (const float*)d_in[18];
    const float* ln_b  = (const float*)d_in[19];
    (void)in_sizes; (void)n_in; (void)out_size;

    float* S = nullptr;
    cudaGetSymbolAddress((void**)&S, g_scratch);
    __nv_bfloat16 *acthi = nullptr, *actlo = nullptr, *w5hi = nullptr, *w5lo = nullptr;
    cudaGetSymbolAddress((void**)&acthi, g_acthi);
    cudaGetSymbolAddress((void**)&actlo, g_actlo);
    cudaGetSymbolAddress((void**)&w5hi, g_w5hi);
    cudaGetSymbolAddress((void**)&w5lo, g_w5lo);

    float* xx   = S + OFF_XX;
    float* xxx  = S + OFF_XXX;
    float* t5   = S + OFF_T5;
    float* xw   = S + OFF_XW;
    float* xk   = S + OFF_XK;
    float* xv   = S + OFF_XV;
    float* xr   = S + OFF_XR;
    float* xg   = S + OFF_XG;
    float* rb   = S + OFF_R;
    float* kb   = S + OFF_K;
    float* vb   = S + OFF_V;
    float* gb   = S + OFF_G;
    float* h1   = S + OFF_H1;
    float* wdec = S + OFF_WDEC;
    float* yb   = S + OFF_Y;
    float* ruk  = S + OFF_RUK;
    float* outp = (float*)d_out;

    const dim3 gTC(C_ / 128, NR_ / 128);   // (6, 64)

    // 0. split all 5 weights
    k_split5<<<(unsigned)(5 * WSZ_ / 256), 256>>>(W_r, W_k, W_v, W_g, W_o, w5hi, w5lo);

    // 1. shift + xxx
    k_shift<<<(unsigned)(NC_ / 256), 256>>>(x, maa_x, xx, xxx);

    // 2. t5 = tanh(xxx @ maa_w1)
    k_gemm<1, false><<<dim3(2, NR_ / 128), 256>>>(xxx, maa_w1, t5, NR_, 160, C_, nullptr);

    // 3. token mix -> xw,xk,xv,xr,xg (fp32)
    k_mix<<<dim3(NR_ / 32, C_ / 128), 256>>>(x, xx, t5, maa_w2,
                                             maa_w, maa_k, maa_v, maa_r, maa_g,
                                             xw, xk, xv, xr, xg);

    // 3b. batched activation split (xk..xg contiguous = 4*NC_)
    k_split4<<<(unsigned)(NC_ / 256), 256>>>(xk, acthi, actlo);

    // 4. big NT GEMMs (bf16-split mma.sync). act slots: 0=k,1=v,2=r,3=g
    k_gemm_mma<<<gTC, 256>>>(acthi + 2 * NC_, actlo + 2 * NC_,
                             w5hi + 0 * WSZ_, w5lo + 0 * WSZ_, rb, 0);
    k_gemm_mma<<<gTC, 256>>>(acthi + 0 * NC_, actlo + 0 * NC_,
                             w5hi + 1 * WSZ_, w5lo + 1 * WSZ_, kb, 0);
    k_gemm_mma<<<gTC, 256>>>(acthi + 1 * NC_, actlo + 1 * NC_,
                             w5hi + 2 * WSZ_, w5lo + 2 * WSZ_, vb, 0);
    k_gemm_mma<<<gTC, 256>>>(acthi + 3 * NC_, actlo + 3 * NC_,
                             w5hi + 3 * WSZ_, w5lo + 3 * WSZ_, gb, 1);  // relu

    // 5. decay path (small fp32 GEMMs)
    k_gemm<1, false><<<dim3(1, NR_ / 128), 256>>>(xw, dec_w1, h1, NR_, 64, C_, nullptr);
    k_gemm<3, false><<<dim3(C_ / 128, NR_ / 128), 256>>>(h1, dec_w2, wdec, NR_, C_, 64, tdec);

    // 6. wkv recurrence
    k_ruk<<<NR_, C_>>>(rb, kb, faaaa, ruk);
    k_wkv<<<B_ * H_, 256>>>(rb, kb, vb, wdec, ruk, yb);

    // 7. groupnorm * g -> bf16 pair (reuse act slot 0)
    k_gnorm<<<NR_, C_>>>(yb, gb, ln_w, ln_b, acthi, actlo);

    // 8. out = yn @ W_o^T
    k_gemm_mma<<<gTC, 256>>>(acthi, actlo,
                             w5hi + 4 * WSZ_, w5lo + 4 * WSZ_, outp, 0);
}